// round 5
// baseline (speedup 1.0000x reference)
#include <cuda_runtime.h>
#include <cstdint>

#define NBATCH 32
#define HROWS 128      // channels
#define HCOLS 76       // [0,4) halo | [4,68) owned 64 cols | 68 = t128 (th1) / halo | pad
#define PCH   18       // per-worker partial chunk (u64), 16B aligned
#define NTHREADS 512
#define NITER 131

typedef unsigned long long u64t;

// ---------- packed f32x2 helpers ----------
__device__ __forceinline__ u64t pk2(float a, float b){
    u64t r; asm("mov.b64 %0, {%1, %2};" : "=l"(r) : "f"(a), "f"(b)); return r;
}
__device__ __forceinline__ void fma2(u64t& d, u64t a, u64t b){
    asm("fma.rn.f32x2 %0, %1, %2, %0;" : "+l"(d) : "l"(a), "l"(b));
}
__device__ __forceinline__ u64t add2(u64t a, u64t b){
    u64t r; asm("add.rn.f32x2 %0, %1, %2;" : "=l"(r) : "l"(a), "l"(b)); return r;
}
__device__ __forceinline__ void unpk2(u64t v, float& a, float& b){
    asm("mov.b64 {%0, %1}, %2;" : "=f"(a), "=f"(b) : "l"(v));
}
__device__ __forceinline__ float lo2(u64t v){ float a,b; unpk2(v,a,b); return a; }
__device__ __forceinline__ float hi2(u64t v){ float a,b; unpk2(v,a,b); return b; }

__device__ __forceinline__ uint32_t mapa32(uint32_t addr, uint32_t rank){
    uint32_t r; asm("mapa.shared::cluster.u32 %0, %1, %2;" : "=r"(r) : "r"(addr), "r"(rank));
    return r;
}
__device__ __forceinline__ void st_cl_f32(uint32_t addr, float v){
    asm volatile("st.shared::cluster.f32 [%0], %1;" :: "r"(addr), "f"(v) : "memory");
}
__device__ __forceinline__ void st_cl_u64(uint32_t addr, u64t v){
    asm volatile("st.shared::cluster.b64 [%0], %1;" :: "r"(addr), "l"(v) : "memory");
}

#define CLUSTER_SYNC() do { \
    asm volatile("barrier.cluster.arrive.aligned;" ::: "memory"); \
    asm volatile("barrier.cluster.wait.aligned;"   ::: "memory"); } while(0)

// One residual dilated-conv iteration.
// Thread decode: og_lo=tid[0:3), ttlo=tid[3:5), cg=tid[5:7), tthi=tid[7], oghi=tid[8].
// og = oghi*8+og_lo (16 o-groups x 4 out-ch), tt = tthi*4+ttlo (8 t-tiles x 8 cols).
// Per warp: 8 og x 4 ttlo -> weight LDS.128 = 128B (1 wf), h LDS.128 = 4x16B (1 wf).
template<int D>
__device__ __forceinline__ void conv_iter(
    float* __restrict__ hbuf, uint32_t hbuf_sh,
    const float* __restrict__ ws, const float* __restrict__ cb,
    u64t* __restrict__ pbuf, float* __restrict__ pbuf2,
    uint32_t oP_base, uint32_t tPa_base, uint32_t tPb_base,
    int th, int ob)
{
    const int tid   = threadIdx.x;
    const int og    = ((tid >> 8) & 1)*8 + (tid & 7);
    const int tt    = ((tid >> 7) & 1)*4 + ((tid >> 3) & 3);
    const int cg    = (tid >> 5) & 3;
    const int lt    = og*8 + tt;
    const bool sp   = (th == 1) && (tt == 7);   // also produce t=128

    u64t acc[4][4];
    #pragma unroll
    for (int oi = 0; oi < 4; oi++)
        #pragma unroll
        for (int p = 0; p < 4; p++) acc[oi][p] = 0ull;
    float accx[4] = {0.f, 0.f, 0.f, 0.f};

    // window: 16 floats = local cols [tt*8, tt*8+16); owned outputs at s[4..11]
    const char*   hb = (const char*)(hbuf + (cg*32)*HCOLS + tt*8);
    const float4* wq = (const float4*)ws + (cg*32*3)*16 + og;   // ws[(c*3+k)*64 + o]

    #pragma unroll 2
    for (int cc = 0; cc < 32; cc++){
        ulonglong2 a0 = *(const ulonglong2*)(hb);
        ulonglong2 a1 = *(const ulonglong2*)(hb + 16);
        ulonglong2 a2 = *(const ulonglong2*)(hb + 32);
        ulonglong2 a3 = *(const ulonglong2*)(hb + 48);
        float4 w0 = wq[0], w1 = wq[16], w2 = wq[32];
        u64t u[8] = {a0.x, a0.y, a1.x, a1.y, a2.x, a2.y, a3.x, a3.y};

        if (D != 1){
            constexpr int S0 = (D == 4) ? 0 : 1;
            constexpr int S2 = (D == 4) ? 4 : 3;
            #define DOO(oi, v0, v1, v2) do {                                   \
                u64t d0 = pk2((v0),(v0)), d1 = pk2((v1),(v1)), d2 = pk2((v2),(v2)); \
                fma2(acc[oi][0], d0, u[S0+0]); fma2(acc[oi][1], d0, u[S0+1]);  \
                fma2(acc[oi][2], d0, u[S0+2]); fma2(acc[oi][3], d0, u[S0+3]);  \
                fma2(acc[oi][0], d1, u[2]);    fma2(acc[oi][1], d1, u[3]);     \
                fma2(acc[oi][2], d1, u[4]);    fma2(acc[oi][3], d1, u[5]);     \
                fma2(acc[oi][0], d2, u[S2+0]); fma2(acc[oi][1], d2, u[S2+1]);  \
                fma2(acc[oi][2], d2, u[S2+2]); fma2(acc[oi][3], d2, u[S2+3]);  \
            } while(0)
            DOO(0, w0.x, w1.x, w2.x);
            DOO(1, w0.y, w1.y, w2.y);
            DOO(2, w0.z, w1.z, w2.z);
            DOO(3, w0.w, w1.w, w2.w);
            #undef DOO
        } else {
            float s[16];
            #pragma unroll
            for (int j = 0; j < 8; j++) unpk2(u[j], s[2*j], s[2*j+1]);
            u64t om[6];
            #pragma unroll
            for (int j = 1; j < 6; j++) om[j] = pk2(s[2*j+1], s[2*j+2]);
            #define DOO1(oi, v0, v1, v2) do {                                  \
                u64t d0 = pk2((v0),(v0)), d1 = pk2((v1),(v1)), d2 = pk2((v2),(v2)); \
                fma2(acc[oi][0], d0, om[1]); fma2(acc[oi][1], d0, om[2]);      \
                fma2(acc[oi][2], d0, om[3]); fma2(acc[oi][3], d0, om[4]);      \
                fma2(acc[oi][0], d1, u[2]);  fma2(acc[oi][1], d1, u[3]);       \
                fma2(acc[oi][2], d1, u[4]);  fma2(acc[oi][3], d1, u[5]);       \
                fma2(acc[oi][0], d2, om[2]); fma2(acc[oi][1], d2, om[3]);      \
                fma2(acc[oi][2], d2, om[4]); fma2(acc[oi][3], d2, om[5]);      \
            } while(0)
            DOO1(0, w0.x, w1.x, w2.x);
            DOO1(1, w0.y, w1.y, w2.y);
            DOO1(2, w0.z, w1.z, w2.z);
            DOO1(3, w0.w, w1.w, w2.w);
            #undef DOO1
        }

        if (sp){
            // t=128: local col 68 = s[12]; taps t-D = s[12-D], t = s[12]; t+D >= 129 -> 0
            const float tm = (D == 4) ? lo2(u[4]) : (D == 2 ? lo2(u[5]) : hi2(u[5]));
            const float tz = lo2(u[6]);
            accx[0] = fmaf(w0.x, tm, fmaf(w1.x, tz, accx[0]));
            accx[1] = fmaf(w0.y, tm, fmaf(w1.y, tz, accx[1]));
            accx[2] = fmaf(w0.z, tm, fmaf(w1.z, tz, accx[2]));
            accx[3] = fmaf(w0.w, tm, fmaf(w1.w, tz, accx[3]));
        }

        hb += HCOLS*4;
        wq += 48;
    }

    // ---- store partials (cg>0) ----
    if (cg != 0){
        u64t* pb = pbuf + (cg - 1)*(128*PCH) + lt*PCH;
        #pragma unroll
        for (int oi = 0; oi < 4; oi++){
            *(ulonglong2*)(pb + oi*4)     = make_ulonglong2(acc[oi][0], acc[oi][1]);
            *(ulonglong2*)(pb + oi*4 + 2) = make_ulonglong2(acc[oi][2], acc[oi][3]);
        }
    }
    if (sp){
        #pragma unroll
        for (int oi = 0; oi < 4; oi++)
            pbuf2[cg*64 + og*4 + oi] = accx[oi];
    }
    __syncthreads();

    // ---- cg0: reduce in registers ----
    if (cg == 0){
        #pragma unroll
        for (int q = 0; q < 3; q++){
            const u64t* pb = pbuf + q*(128*PCH) + lt*PCH;
            #pragma unroll
            for (int oi = 0; oi < 4; oi++){
                ulonglong2 v0 = *(const ulonglong2*)(pb + oi*4);
                ulonglong2 v1 = *(const ulonglong2*)(pb + oi*4 + 2);
                acc[oi][0] = add2(acc[oi][0], v0.x);
                acc[oi][1] = add2(acc[oi][1], v0.y);
                acc[oi][2] = add2(acc[oi][2], v1.x);
                acc[oi][3] = add2(acc[oi][3], v1.y);
            }
        }
    }

    CLUSTER_SYNC();   // (A) all reads of h (incl. peers') complete cluster-wide

    if (cg == 0){
        #pragma unroll
        for (int oi = 0; oi < 4; oi++){
            const int   ol   = og*4 + oi;
            const int   row  = ob + ol;
            const float bias = cb[ol];
            float* own = hbuf + row*HCOLS + 4 + tt*8;
            const uint32_t off0 = (uint32_t)(row*HCOLS + 4 + tt*8) * 4u;
            float hn[8];
            #pragma unroll
            for (int p = 0; p < 4; p++){
                float r0, r1; unpk2(acc[oi][p], r0, r1);
                float2 hol = *(const float2*)(own + 2*p);
                hn[2*p]   = fmaxf(r0 + bias, 0.f) + hol.x;
                hn[2*p+1] = fmaxf(r1 + bias, 0.f) + hol.y;
                *(float2*)(own + 2*p) = make_float2(hn[2*p], hn[2*p+1]);
                st_cl_u64(oP_base + off0 + 8u*p, pk2(hn[2*p], hn[2*p+1]));
            }
            // halo edges to the other-t CTAs
            if (th == 0 && tt == 7){
                #pragma unroll
                for (int j = 4; j < 8; j++){   // t = 60..63 -> peer local col j-4
                    const uint32_t eo = (uint32_t)(row*HCOLS + (j - 4)) * 4u;
                    st_cl_f32(tPa_base + eo, hn[j]);
                    st_cl_f32(tPb_base + eo, hn[j]);
                }
            }
            if (th == 1 && tt == 0){
                #pragma unroll
                for (int j = 0; j < 4; j++){   // t = 64..67 -> peer local col 68+j
                    const uint32_t eo = (uint32_t)(row*HCOLS + 68 + j) * 4u;
                    st_cl_f32(tPa_base + eo, hn[j]);
                    st_cl_f32(tPb_base + eo, hn[j]);
                }
            }
        }
    }
    // t=128 finalize (th1 CTAs)
    if (th == 1 && tid < 64){
        float s = pbuf2[tid] + pbuf2[64 + tid] + pbuf2[128 + tid] + pbuf2[192 + tid];
        const int row = ob + tid;
        float v = fmaxf(s + cb[tid], 0.f) + hbuf[row*HCOLS + 68];
        hbuf[row*HCOLS + 68] = v;
        st_cl_f32(oP_base + (uint32_t)(row*HCOLS + 68)*4u, v);
    }

    CLUSTER_SYNC();   // (B) all h_new writes (local + DSMEM) visible cluster-wide
}

__global__ void __cluster_dims__(4, 1, 1) __launch_bounds__(NTHREADS, 1)
vgt_kernel(const int* __restrict__ x, const float* __restrict__ emb_w,
           const float* __restrict__ red_w, const float* __restrict__ red_b,
           const float* __restrict__ conv_w, const float* __restrict__ conv_b,
           const float* __restrict__ out_w, const float* __restrict__ out_b,
           float* __restrict__ out)
{
    extern __shared__ __align__(16) unsigned char smraw[];
    u64t*  pbuf  = (u64t*)smraw;                       // 3*128*18 u64 = 55296B
    float* hbuf  = (float*)(pbuf + 3*128*PCH);         // 128*76 = 9728 f
    float* ws    = hbuf + HROWS*HCOLS;                 // 24576 f
    float* cb    = ws + 24576;                         // 64 f
    float* pbuf2 = cb + 64;                            // 256 f
    float* m1    = (float*)pbuf;                       // overlay (prologue only)
    float* m2    = m1 + 1280;

    const int tid = threadIdx.x;
    const int b   = blockIdx.x >> 2;
    const int g   = blockIdx.x & 3;
    const int oh  = g >> 1;          // o-half
    const int th  = g & 1;           // t-half
    const int ob  = oh * 64;         // my produced channels [ob, ob+64)
    const int T0  = th * 64;         // my owned t cols [T0, T0+64) (+ t=128 for th1)

    const uint32_t hbuf_sh = (uint32_t)__cvta_generic_to_shared(hbuf);
    const uint32_t oP_base  = mapa32(hbuf_sh, (uint32_t)(((oh ^ 1) << 1) | th));
    const uint32_t tPa_base = mapa32(hbuf_sh, (uint32_t)((oh << 1) | (th ^ 1)));
    const uint32_t tPb_base = mapa32(hbuf_sh, (uint32_t)(((oh ^ 1) << 1) | (th ^ 1)));

    // ---- prologue: weights, bias, reducer tables, zero h ----
    for (int idx = tid; idx < 64*128*3; idx += NTHREADS){
        int ol = idx & 63;
        int ck = idx >> 6;          // = c*3 + k
        int k  = ck % 3;
        int c  = ck / 3;
        ws[idx] = conv_w[((ob + ol)*HROWS + c)*3 + k];
    }
    if (tid < 64) cb[tid] = conv_b[ob + tid];

    for (int idx = tid; idx < 1280; idx += NTHREADS){
        int v = idx >> 7;
        int o = idx & 127;
        const float* rw = red_w + o*(2*HROWS);
        const float* ew = emb_w + v*HROWS;
        float s1 = 0.f, s2 = 0.f;
        for (int c = 0; c < HROWS; c++){
            float e = ew[c];
            s1 = fmaf(rw[c],         e, s1);
            s2 = fmaf(rw[HROWS + c], e, s2);
        }
        m1[idx] = s1;
        m2[idx] = s2;
    }
    for (int idx = tid; idx < HROWS*HCOLS; idx += NTHREADS) hbuf[idx] = 0.f;
    __syncthreads();

    // ---- h0 = relu(M1[x[t]] + M2[x[t+128]] + red_b), incl. own halos ----
    {
        const int* xb = x + b*256;
        for (int idx = tid; idx < HROWS*72; idx += NTHREADS){
            int o  = idx & 127;
            int ci = idx >> 7;           // local col in [0,72)
            int t  = T0 - 4 + ci;
            if (t >= 0 && t < 128){
                int v1 = xb[t];
                int v2 = xb[t + 128];
                float val = m1[v1*128 + o] + m2[v2*128 + o] + red_b[o];
                hbuf[o*HCOLS + ci] = fmaxf(val, 0.f);
            }
        }
    }
    __syncthreads();

    // ---- 131 residual conv iterations, all state smem-resident ----
    #pragma unroll 1
    for (int i = 0; i < 4; i++)
        conv_iter<1>(hbuf, hbuf_sh, ws, cb, pbuf, pbuf2, oP_base, tPa_base, tPb_base, th, ob);
    #pragma unroll 1
    for (int i = 0; i < 4; i++)
        conv_iter<2>(hbuf, hbuf_sh, ws, cb, pbuf, pbuf2, oP_base, tPa_base, tPb_base, th, ob);
    #pragma unroll 1
    for (int i = 0; i < NITER - 8; i++)
        conv_iter<4>(hbuf, hbuf_sh, ws, cb, pbuf, pbuf2, oP_base, tPa_base, tPb_base, th, ob);

    // ---- output head: out[b,t,o] = sum_c out_w[o,c]*h[c,t] + out_b[o] ----
    {
        const int tbase = T0 + oh*32;
        const int cnt   = 32 + ((th == 1 && oh == 1) ? 1 : 0);   // th1/oh1 also t=128
        for (int idx = tid; idx < cnt*10; idx += NTHREADS){
            int tl = idx / 10;
            int o  = idx % 10;
            int t  = tbase + tl;
            int col = t - T0 + 4;
            const float* wrow = out_w + o*HROWS;
            float s = out_b[o];
            #pragma unroll 8
            for (int c = 0; c < HROWS; c++)
                s = fmaf(__ldg(wrow + c), hbuf[c*HCOLS + col], s);
            out[(b*129 + t)*10 + o] = s;
        }
    }
}

extern "C" void kernel_launch(void* const* d_in, const int* in_sizes, int n_in,
                              void* d_out, int out_size)
{
    (void)in_sizes; (void)n_in; (void)out_size;
    const int*   x      = (const int*)  d_in[0];
    const float* emb_w  = (const float*)d_in[1];
    const float* red_w  = (const float*)d_in[2];
    const float* red_b  = (const float*)d_in[3];
    const float* conv_w = (const float*)d_in[4];
    const float* conv_b = (const float*)d_in[5];
    const float* out_w  = (const float*)d_in[6];
    const float* out_b  = (const float*)d_in[7];
    float* out = (float*)d_out;

    const size_t smem = (size_t)(3*128*PCH)*sizeof(u64t) +
        (size_t)(HROWS*HCOLS + 24576 + 64 + 256) * sizeof(float);   // ~189.3 KB
    cudaFuncSetAttribute(vgt_kernel, cudaFuncAttributeMaxDynamicSharedMemorySize, (int)smem);
    vgt_kernel<<<NBATCH*4, NTHREADS, smem>>>(x, emb_w, red_w, red_b,
                                             conv_w, conv_b, out_w, out_b, out);
}

// round 6
// speedup vs baseline: 1.3208x; 1.3208x over previous
#include <cuda_runtime.h>
#include <cstdint>

#define NB   32
#define NH   128
#define TPF  144      // floats per channel row: [0,4) halo | [4,133) t=0..128 | zero tail
#define HALO 4
#define NITER 131
#define NTHREADS 512

typedef unsigned long long u64t;

// Double-buffered hidden state (L2-resident). Halos stay zero forever.
__device__ float g_h[2][NB][NH][TPF];

// hs layout: channel c at float offset c*144 + (c>=64 ? 16 : 0)  (64B pad between halves)
#define HS_CH1   9232          // 64*144 + 16
#define HS_FLOATS 18448
// ws2 layout: ((c*3+k)*32 + o) + (c>=64 ? 16 : 0)   (o local in [0,32), float pairs per og)
#define WS_CH1   6160          // 64*96 + 16
#define WS_FLOATS 12304

// ---------- packed f32x2 helpers ----------
__device__ __forceinline__ u64t pk2(float a, float b){
    u64t r; asm("mov.b64 %0, {%1, %2};" : "=l"(r) : "f"(a), "f"(b)); return r;
}
__device__ __forceinline__ void fma2(u64t& d, u64t a, u64t b){
    asm("fma.rn.f32x2 %0, %1, %2, %0;" : "+l"(d) : "l"(a), "l"(b));
}
__device__ __forceinline__ void unpk2(u64t v, float& a, float& b){
    asm("mov.b64 {%0, %1}, %2;" : "=f"(a), "=f"(b) : "l"(v));
}
__device__ __forceinline__ float lo2(u64t v){ float a,b; unpk2(v,a,b); return a; }
__device__ __forceinline__ float hi2(u64t v){ float a,b; unpk2(v,a,b); return b; }
__device__ __forceinline__ void cp16(uint32_t d, const void* s){
    asm volatile("cp.async.cg.shared.global [%0], [%1], 16;" :: "r"(d), "l"(s));
}

#define CLUSTER_SYNC() do { \
    asm volatile("barrier.cluster.arrive.aligned;" ::: "memory"); \
    asm volatile("barrier.cluster.wait.aligned;"   ::: "memory"); } while(0)

// One residual dilated-conv iteration.
// Lane bits: og_lo=lane[0:3), ch=lane[3], ttlo=lane[4]. Warp: oghi=w[0], tthi=w[1:4).
// Thread tile: 2 out-ch (o = og*2+{0,1}) x 8 t (t0=tt*8), summed over its 64-channel half,
// then shfl.bfly over lane bit 3 completes the 128-channel sum. No smem reduction.
template<int D>
__device__ __forceinline__ void conv_iter(
    const float* __restrict__ src, float* __restrict__ dst,
    float* __restrict__ hs, uint32_t hs_sh,
    const float* __restrict__ ws2, const float* __restrict__ cb,
    int obase, int padE)
{
    const int tid = threadIdx.x;

    // ---- stage full h (73.7 KB) from L2 into padded smem ----
    #pragma unroll
    for (int i = 0; i < 9; i++){
        const int j = tid + i*NTHREADS;                       // 16B chunk index
        const uint32_t d = hs_sh + (uint32_t)j*16u + ((j >= 2304) ? 64u : 0u);
        cp16(d, (const char*)src + (size_t)j*16);
    }
    asm volatile("cp.async.commit_group;\n\tcp.async.wait_group 0;" ::: "memory");
    __syncthreads();

    const int lane = tid & 31;
    const int w    = tid >> 5;
    const int og   = ((w & 1) << 3) | (lane & 7);             // 0..15
    const int ch   = (lane >> 3) & 1;
    const int tt   = (((w >> 1) & 7) << 1) | ((lane >> 4) & 1);
    const int t0   = tt * 8;
    const bool sp128 = (tt == 15);                            // also produce t=128

    u64t acc[2][4] = {{0ull,0ull,0ull,0ull},{0ull,0ull,0ull,0ull}};
    float accx[2] = {0.f, 0.f};

    // window: 16 floats = cols [t0, t0+16); owned outputs at window cols [4,12)
    const char*  hb = (const char*)(hs + ch*HS_CH1 + t0);
    const float* wb = ws2 + ch*WS_CH1 + og*2;

    #pragma unroll 2
    for (int cc = 0; cc < 64; cc++){
        ulonglong2 a0 = *(const ulonglong2*)(hb);
        ulonglong2 a1 = *(const ulonglong2*)(hb + 16);
        ulonglong2 a2 = *(const ulonglong2*)(hb + 32);
        ulonglong2 a3 = *(const ulonglong2*)(hb + 48);
        float2 w0 = *(const float2*)(wb);
        float2 w1 = *(const float2*)(wb + 32);
        float2 w2 = *(const float2*)(wb + 64);
        u64t u[8] = {a0.x, a0.y, a1.x, a1.y, a2.x, a2.y, a3.x, a3.y};

        if (D != 1){
            constexpr int S0 = (D == 4) ? 0 : 1;
            constexpr int S2 = (D == 4) ? 4 : 3;
            #define DOO(oi, v0, v1, v2) do {                                   \
                u64t d0 = pk2((v0),(v0)), d1 = pk2((v1),(v1)), d2 = pk2((v2),(v2)); \
                fma2(acc[oi][0], d0, u[S0+0]); fma2(acc[oi][1], d0, u[S0+1]);  \
                fma2(acc[oi][2], d0, u[S0+2]); fma2(acc[oi][3], d0, u[S0+3]);  \
                fma2(acc[oi][0], d1, u[2]);    fma2(acc[oi][1], d1, u[3]);     \
                fma2(acc[oi][2], d1, u[4]);    fma2(acc[oi][3], d1, u[5]);     \
                fma2(acc[oi][0], d2, u[S2+0]); fma2(acc[oi][1], d2, u[S2+1]);  \
                fma2(acc[oi][2], d2, u[S2+2]); fma2(acc[oi][3], d2, u[S2+3]);  \
            } while(0)
            DOO(0, w0.x, w1.x, w2.x);
            DOO(1, w0.y, w1.y, w2.y);
            #undef DOO
        } else {
            float s[16];
            #pragma unroll
            for (int j = 0; j < 8; j++) unpk2(u[j], s[2*j], s[2*j+1]);
            u64t om[6];
            #pragma unroll
            for (int j = 1; j < 6; j++) om[j] = pk2(s[2*j+1], s[2*j+2]);
            #define DOO1(oi, v0, v1, v2) do {                                  \
                u64t d0 = pk2((v0),(v0)), d1 = pk2((v1),(v1)), d2 = pk2((v2),(v2)); \
                fma2(acc[oi][0], d0, om[1]); fma2(acc[oi][1], d0, om[2]);      \
                fma2(acc[oi][2], d0, om[3]); fma2(acc[oi][3], d0, om[4]);      \
                fma2(acc[oi][0], d1, u[2]);  fma2(acc[oi][1], d1, u[3]);       \
                fma2(acc[oi][2], d1, u[4]);  fma2(acc[oi][3], d1, u[5]);       \
                fma2(acc[oi][0], d2, om[2]); fma2(acc[oi][1], d2, om[3]);      \
                fma2(acc[oi][2], d2, om[4]); fma2(acc[oi][3], d2, om[5]);      \
            } while(0)
            DOO1(0, w0.x, w1.x, w2.x);
            DOO1(1, w0.y, w1.y, w2.y);
            #undef DOO1
        }

        if (sp128){
            // t=128 at window col 12; tap t-D at col 12-D; tap t+D is zero halo
            const float tm = (D == 4) ? lo2(u[4]) : (D == 2 ? lo2(u[5]) : hi2(u[5]));
            const float tz = lo2(u[6]);
            accx[0] = fmaf(w0.x, tm, fmaf(w1.x, tz, accx[0]));
            accx[1] = fmaf(w0.y, tm, fmaf(w1.y, tz, accx[1]));
        }

        hb += TPF*4;
        wb += 96;
    }

    // ---- complete 128-channel sums: butterfly over the ch lane bit ----
    float res[2][8];
    #pragma unroll
    for (int oi = 0; oi < 2; oi++)
        #pragma unroll
        for (int p = 0; p < 4; p++){
            float a, b; unpk2(acc[oi][p], a, b);
            a += __shfl_xor_sync(0xffffffffu, a, 8);
            b += __shfl_xor_sync(0xffffffffu, b, 8);
            res[oi][2*p] = a; res[oi][2*p+1] = b;
        }
    accx[0] += __shfl_xor_sync(0xffffffffu, accx[0], 8);
    accx[1] += __shfl_xor_sync(0xffffffffu, accx[1], 8);

    // ---- epilogue: bias + relu + residual, write slice to dst (L2) ----
    if (ch == 0){
        #pragma unroll
        for (int oi = 0; oi < 2; oi++){
            const int   ol   = og*2 + oi;
            const int   row  = obase + ol;
            const float bias = cb[ol];
            const float* hold = hs  + row*TPF + padE + HALO + t0;
            float*       dr   = dst + row*TPF + HALO + t0;
            float4 h0 = *(const float4*)hold;
            float4 h1 = *(const float4*)(hold + 4);
            float4 v0, v1;
            v0.x = fmaxf(res[oi][0] + bias, 0.f) + h0.x;
            v0.y = fmaxf(res[oi][1] + bias, 0.f) + h0.y;
            v0.z = fmaxf(res[oi][2] + bias, 0.f) + h0.z;
            v0.w = fmaxf(res[oi][3] + bias, 0.f) + h0.w;
            v1.x = fmaxf(res[oi][4] + bias, 0.f) + h1.x;
            v1.y = fmaxf(res[oi][5] + bias, 0.f) + h1.y;
            v1.z = fmaxf(res[oi][6] + bias, 0.f) + h1.z;
            v1.w = fmaxf(res[oi][7] + bias, 0.f) + h1.w;
            __stcg((float4*)dr, v0);
            __stcg((float4*)(dr + 4), v1);
            if (sp128)
                __stcg(dr + 8, fmaxf(accx[oi] + bias, 0.f) + hold[8]);   // t=128, col 132
        }
    }
}

__global__ void __cluster_dims__(4, 1, 1) __launch_bounds__(NTHREADS, 1)
vgt_kernel(const int* __restrict__ x, const float* __restrict__ emb_w,
           const float* __restrict__ red_w, const float* __restrict__ red_b,
           const float* __restrict__ conv_w, const float* __restrict__ conv_b,
           const float* __restrict__ out_w, const float* __restrict__ out_b,
           float* __restrict__ out)
{
    extern __shared__ __align__(16) float sm[];
    float* hs  = sm;                    // 18448 floats (padded h)
    float* ws2 = hs + HS_FLOATS;        // 12304
    float* cb  = ws2 + WS_FLOATS;       // 32
    float* m1  = cb + 32;               // 320
    float* m2  = m1 + 320;              // 320

    const uint32_t hs_sh = (uint32_t)__cvta_generic_to_shared(hs);

    const int tid   = threadIdx.x;
    const int b     = blockIdx.x >> 2;
    const int g     = blockIdx.x & 3;
    const int obase = g * 32;
    const int padE  = (g >= 2) ? 16 : 0;

    // ---- prologue: weights (padded layout), bias, reducer tables, zero state ----
    for (int idx = tid; idx < NH*3*32; idx += NTHREADS){
        int o  = idx & 31;
        int ck = idx >> 5;          // = c*3 + k
        int k  = ck % 3;
        int c  = ck / 3;
        ws2[idx + ((c >= 64) ? 16 : 0)] = conv_w[((obase + o)*NH + c)*3 + k];
    }
    if (tid < 32) cb[tid] = conv_b[obase + tid];

    for (int idx = tid; idx < 10*32; idx += NTHREADS){
        int v = idx >> 5;
        int o = idx & 31;
        const float* rw = red_w + (obase + o)*(2*NH);
        const float* ew = emb_w + v*NH;
        float s1 = 0.f, s2 = 0.f;
        for (int c = 0; c < NH; c++){
            float e = ew[c];
            s1 = fmaf(rw[c],      e, s1);
            s2 = fmaf(rw[NH + c], e, s2);
        }
        m1[idx] = s1;
        m2[idx] = s2;
    }

    for (int idx = tid; idx < 2*32*TPF; idx += NTHREADS){
        int bb = idx / (32*TPF);
        int r  = idx - bb*(32*TPF);
        int c  = r / TPF;
        int t  = r - c*TPF;
        __stcg(&g_h[bb][b][obase + c][t], 0.f);
    }
    __syncthreads();

    // ---- h0 = relu(M1[x[t]] + M2[x[t+128]] + red_b) ----
    {
        const int* xb = x + b*256;
        for (int idx = tid; idx < 32*128; idx += NTHREADS){
            int o = idx >> 7;
            int t = idx & 127;
            int v1 = xb[t];
            int v2 = xb[t + 128];
            float val = m1[v1*32 + o] + m2[v2*32 + o] + red_b[obase + o];
            __stcg(&g_h[0][b][obase + o][HALO + t], fmaxf(val, 0.f));
        }
    }
    CLUSTER_SYNC();

    // ---- 131 residual conv iterations ----
    int cur = 0;
    #pragma unroll 1
    for (int i = 0; i < 4; i++){
        conv_iter<1>(&g_h[cur][b][0][0], &g_h[cur^1][b][0][0], hs, hs_sh, ws2, cb, obase, padE);
        CLUSTER_SYNC();
        cur ^= 1;
    }
    #pragma unroll 1
    for (int i = 0; i < 4; i++){
        conv_iter<2>(&g_h[cur][b][0][0], &g_h[cur^1][b][0][0], hs, hs_sh, ws2, cb, obase, padE);
        CLUSTER_SYNC();
        cur ^= 1;
    }
    #pragma unroll 1
    for (int i = 0; i < NITER - 8; i++){
        conv_iter<4>(&g_h[cur][b][0][0], &g_h[cur^1][b][0][0], hs, hs_sh, ws2, cb, obase, padE);
        CLUSTER_SYNC();
        cur ^= 1;
    }

    // ---- output head: restage final h, out[b,t,o] = out_w . h[:,t] + out_b ----
    #pragma unroll
    for (int i = 0; i < 9; i++){
        const int j = tid + i*NTHREADS;
        const uint32_t d = hs_sh + (uint32_t)j*16u + ((j >= 2304) ? 64u : 0u);
        cp16(d, (const char*)&g_h[cur][b][0][0] + (size_t)j*16);
    }
    asm volatile("cp.async.commit_group;\n\tcp.async.wait_group 0;" ::: "memory");
    __syncthreads();

    const int tstart = g * 33;
    const int tcnt   = (129 - tstart) < 33 ? (129 - tstart) : 33;
    for (int idx = tid; idx < tcnt*10; idx += NTHREADS){
        int t = tstart + idx / 10;
        int o = idx % 10;
        const float* wrow = out_w + o*NH;
        float s = out_b[o];
        #pragma unroll 8
        for (int c = 0; c < NH; c++)
            s = fmaf(__ldg(wrow + c), hs[c*TPF + ((c >= 64) ? 16 : 0) + HALO + t], s);
        out[(b*129 + t)*10 + o] = s;
    }
}

extern "C" void kernel_launch(void* const* d_in, const int* in_sizes, int n_in,
                              void* d_out, int out_size)
{
    (void)in_sizes; (void)n_in; (void)out_size;
    const int*   x      = (const int*)  d_in[0];
    const float* emb_w  = (const float*)d_in[1];
    const float* red_w  = (const float*)d_in[2];
    const float* red_b  = (const float*)d_in[3];
    const float* conv_w = (const float*)d_in[4];
    const float* conv_b = (const float*)d_in[5];
    const float* out_w  = (const float*)d_in[6];
    const float* out_b  = (const float*)d_in[7];
    float* out = (float*)d_out;

    const size_t smem = (size_t)(HS_FLOATS + WS_FLOATS + 32 + 320 + 320) * sizeof(float); // ~125.7 KB
    cudaFuncSetAttribute(vgt_kernel, cudaFuncAttributeMaxDynamicSharedMemorySize, (int)smem);
    vgt_kernel<<<NB*4, NTHREADS, smem>>>(x, emb_w, red_w, red_b,
                                         conv_w, conv_b, out_w, out_b, out);
}